// round 1
// baseline (speedup 1.0000x reference)
#include <cuda_runtime.h>
#include <math.h>

// Problem constants
#define NUM_CARDS 30000
#define CARD_DIM  512
#define HIDDEN    512
#define EMBED     256
#define BATCH     256
#define CUBE_S    360
#define NM1       29999          // NUM_CARDS - 1
#define DEC_ELEMS (BATCH * NM1)  // 7,679,744

// Scratch (device globals -- no allocation allowed)
__device__ float g_He[NUM_CARDS * HIDDEN];     // relu(cards @ W_e1 + b_e1)
__device__ float g_Ht[NUM_CARDS * HIDDEN];     // relu(cards @ W_t1 + b_t1)
__device__ float g_trans[NUM_CARDS * EMBED];   // transformed cards (rows 0..29998 used), normalized in place
__device__ float g_encn[BATCH * EMBED];        // l2-normalized encoded cube

// ---------------------------------------------------------------------------
// Generic NN SGEMM: C[M,N] = epi(A[M,K] @ B[K,N] + bias[N])
// BM=BN=128, BK=16, TM=TN=8, 256 threads. Guards on M and N.
// EPI: 0 = relu(x+bias), 1 = x+bias
// ---------------------------------------------------------------------------
template<int EPI>
__global__ __launch_bounds__(256, 2)
void sgemm_nn(const float* __restrict__ A, const float* __restrict__ B,
              const float* __restrict__ bias, float* __restrict__ C,
              int M, int N, int K)
{
    __shared__ float As[16][132];
    __shared__ float Bs[16][132];

    const int tid = threadIdx.x;
    const int m0 = blockIdx.y * 128;
    const int n0 = blockIdx.x * 128;

    const int aRow = tid >> 2;          // 0..63
    const int aCol = (tid & 3) << 2;    // 0,4,8,12
    const int bRow = tid >> 5;          // 0..7
    const int bCol = (tid & 31) << 2;   // 0..124
    const int tRow = (tid >> 4) << 3;   // 0..120
    const int tCol = (tid & 15) << 3;   // 0..120

    float acc[8][8];
    #pragma unroll
    for (int i = 0; i < 8; i++)
        #pragma unroll
        for (int j = 0; j < 8; j++) acc[i][j] = 0.f;

    float ra[8], rb[8];

    for (int k0 = 0; k0 < K; k0 += 16) {
        // Load A tile (transposed into shared)
        #pragma unroll
        for (int i = 0; i < 128; i += 64) {
            int r = m0 + aRow + i;
            float4 v = make_float4(0.f, 0.f, 0.f, 0.f);
            if (r < M) v = *(const float4*)&A[(size_t)r * K + k0 + aCol];
            As[aCol + 0][aRow + i] = v.x;
            As[aCol + 1][aRow + i] = v.y;
            As[aCol + 2][aRow + i] = v.z;
            As[aCol + 3][aRow + i] = v.w;
        }
        // Load B tile
        #pragma unroll
        for (int i = 0; i < 16; i += 8) {
            int c = n0 + bCol;
            float4 v = make_float4(0.f, 0.f, 0.f, 0.f);
            if (c < N) v = *(const float4*)&B[(size_t)(k0 + bRow + i) * N + c];
            *(float4*)&Bs[bRow + i][bCol] = v;
        }
        __syncthreads();

        #pragma unroll
        for (int kk = 0; kk < 16; kk++) {
            #pragma unroll
            for (int i = 0; i < 8; i += 4) *(float4*)&ra[i] = *(const float4*)&As[kk][tRow + i];
            #pragma unroll
            for (int j = 0; j < 8; j += 4) *(float4*)&rb[j] = *(const float4*)&Bs[kk][tCol + j];
            #pragma unroll
            for (int i = 0; i < 8; i++)
                #pragma unroll
                for (int j = 0; j < 8; j++)
                    acc[i][j] = fmaf(ra[i], rb[j], acc[i][j]);
        }
        __syncthreads();
    }

    // Epilogue
    #pragma unroll
    for (int i = 0; i < 8; i++) {
        int r = m0 + tRow + i;
        if (r >= M) continue;
        #pragma unroll
        for (int j = 0; j < 8; j += 4) {
            int c = n0 + tCol + j;
            if (c + 3 < N) {
                float4 v;
                v.x = acc[i][j + 0] + bias[c + 0];
                v.y = acc[i][j + 1] + bias[c + 1];
                v.z = acc[i][j + 2] + bias[c + 2];
                v.w = acc[i][j + 3] + bias[c + 3];
                if (EPI == 0) {
                    v.x = fmaxf(v.x, 0.f); v.y = fmaxf(v.y, 0.f);
                    v.z = fmaxf(v.z, 0.f); v.w = fmaxf(v.w, 0.f);
                }
                *(float4*)&C[(size_t)r * N + c] = v;
            } else {
                #pragma unroll
                for (int q = 0; q < 4; q++) {
                    int cc = c + q;
                    if (cc < N) {
                        float x = acc[i][j + q] + bias[cc];
                        if (EPI == 0) x = fmaxf(x, 0.f);
                        C[(size_t)r * N + cc] = x;
                    }
                }
            }
        }
    }
}

// ---------------------------------------------------------------------------
// Row l2-normalize in place: X[r,:] *= rsqrt(max(sum sq, 1e-12)), cols == 256
// ---------------------------------------------------------------------------
__global__ __launch_bounds__(256)
void norm_rows(float* __restrict__ X, int rows)
{
    int r = blockIdx.x;
    if (r >= rows) return;
    int tid = threadIdx.x;
    __shared__ float red[8];
    float v = X[(size_t)r * 256 + tid];
    float s = v * v;
    #pragma unroll
    for (int o = 16; o > 0; o >>= 1) s += __shfl_xor_sync(0xffffffffu, s, o);
    if ((tid & 31) == 0) red[tid >> 5] = s;
    __syncthreads();
    if (tid == 0) {
        float t = 0.f;
        #pragma unroll
        for (int i = 0; i < 8; i++) t += red[i];
        red[0] = rsqrtf(fmaxf(t, 1e-12f));
    }
    __syncthreads();
    X[(size_t)r * 256 + tid] = v * red[0];
}

// ---------------------------------------------------------------------------
// Per-batch: gather-mean H_e rows -> pooled[512]; encoded = pooled@W_e2+b_e2;
// write encoded to out; store l2-normalized copy to g_encn.
// One block per batch row, 256 threads.
// ---------------------------------------------------------------------------
__global__ __launch_bounds__(256)
void pool_encode(const int* __restrict__ cube, const float* __restrict__ W_e2,
                 const float* __restrict__ b_e2, float* __restrict__ out_enc)
{
    __shared__ float pooled[512];
    __shared__ float red[8];
    int b = blockIdx.x, tid = threadIdx.x;

    float ax = 0.f, ay = 0.f;
    const int* ids = cube + b * CUBE_S;
    for (int s = 0; s < CUBE_S; s++) {
        int c = ids[s];
        float2 v = ((const float2*)(g_He + (size_t)c * HIDDEN))[tid];
        ax += v.x;
        ay += v.y;
    }
    pooled[2 * tid + 0] = ax * (1.0f / (float)CUBE_S);
    pooled[2 * tid + 1] = ay * (1.0f / (float)CUBE_S);
    __syncthreads();

    float e = b_e2[tid];
    #pragma unroll 8
    for (int k = 0; k < 512; k++)
        e = fmaf(pooled[k], W_e2[k * 256 + tid], e);

    out_enc[(size_t)b * 256 + tid] = e;

    float s = e * e;
    #pragma unroll
    for (int o = 16; o > 0; o >>= 1) s += __shfl_xor_sync(0xffffffffu, s, o);
    if ((tid & 31) == 0) red[tid >> 5] = s;
    __syncthreads();
    if (tid == 0) {
        float t = 0.f;
        #pragma unroll
        for (int i = 0; i < 8; i++) t += red[i];
        red[0] = rsqrtf(fmaxf(t, 1e-12f));
    }
    __syncthreads();
    g_encn[(size_t)b * 256 + tid] = e * red[0];
}

// ---------------------------------------------------------------------------
// sims GEMM-NT + sigmoid epilogue:
// out[m,n] = sigmoid((dot(encn[m,:], trans[n,:]) - 0.5) * T)
// A: [256,256] row-major, Bt: [29999,256] row-major. BM=BN=128, BK=16.
// ---------------------------------------------------------------------------
__global__ __launch_bounds__(256, 2)
void sims_kernel(const float* __restrict__ A, const float* __restrict__ Bt,
                 const float* __restrict__ temp, float* __restrict__ out)
{
    const int N = NM1, K = 256;
    __shared__ float As[16][132];
    __shared__ float Bs[16][132];

    const int tid = threadIdx.x;
    const int n0 = blockIdx.x * 128;
    const int m0 = blockIdx.y * 128;

    const int aRow = tid >> 2;          // 0..63
    const int aCol = (tid & 3) << 2;    // 0,4,8,12
    const int tRow = (tid >> 4) << 3;
    const int tCol = (tid & 15) << 3;

    float acc[8][8];
    #pragma unroll
    for (int i = 0; i < 8; i++)
        #pragma unroll
        for (int j = 0; j < 8; j++) acc[i][j] = 0.f;

    float ra[8], rb[8];

    for (int k0 = 0; k0 < K; k0 += 16) {
        #pragma unroll
        for (int i = 0; i < 128; i += 64) {
            int r = m0 + aRow + i;  // always < 256
            float4 v = *(const float4*)&A[(size_t)r * K + k0 + aCol];
            As[aCol + 0][aRow + i] = v.x;
            As[aCol + 1][aRow + i] = v.y;
            As[aCol + 2][aRow + i] = v.z;
            As[aCol + 3][aRow + i] = v.w;
        }
        #pragma unroll
        for (int i = 0; i < 128; i += 64) {
            int n = n0 + aRow + i;
            float4 v = make_float4(0.f, 0.f, 0.f, 0.f);
            if (n < N) v = *(const float4*)&Bt[(size_t)n * K + k0 + aCol];
            Bs[aCol + 0][aRow + i] = v.x;
            Bs[aCol + 1][aRow + i] = v.y;
            Bs[aCol + 2][aRow + i] = v.z;
            Bs[aCol + 3][aRow + i] = v.w;
        }
        __syncthreads();

        #pragma unroll
        for (int kk = 0; kk < 16; kk++) {
            #pragma unroll
            for (int i = 0; i < 8; i += 4) *(float4*)&ra[i] = *(const float4*)&As[kk][tRow + i];
            #pragma unroll
            for (int j = 0; j < 8; j += 4) *(float4*)&rb[j] = *(const float4*)&Bs[kk][tCol + j];
            #pragma unroll
            for (int i = 0; i < 8; i++)
                #pragma unroll
                for (int j = 0; j < 8; j++)
                    acc[i][j] = fmaf(ra[i], rb[j], acc[i][j]);
        }
        __syncthreads();
    }

    const float t = __ldg(temp);
    #pragma unroll
    for (int i = 0; i < 8; i++) {
        int r = m0 + tRow + i;
        #pragma unroll
        for (int j = 0; j < 8; j++) {
            int c = n0 + tCol + j;
            if (c < N) {
                float x = (acc[i][j] - 0.5f) * t;
                out[(size_t)r * N + c] = 1.0f / (1.0f + expf(-x));
            }
        }
    }
}

// ---------------------------------------------------------------------------
// Launch
// Inputs: 0 noisy_cube(int), 1 card_embeddings, 2 W_e1, 3 b_e1, 4 W_e2,
//         5 b_e2, 6 W_t1, 7 b_t1, 8 W_t2, 9 b_t2, 10 temperature
// Output: [decoded 256x29999][encoded 256x256]
// ---------------------------------------------------------------------------
extern "C" void kernel_launch(void* const* d_in, const int* in_sizes, int n_in,
                              void* d_out, int out_size)
{
    const int*   cube  = (const int*)  d_in[0];
    const float* cards = (const float*)d_in[1];
    const float* W_e1  = (const float*)d_in[2];
    const float* b_e1  = (const float*)d_in[3];
    const float* W_e2  = (const float*)d_in[4];
    const float* b_e2  = (const float*)d_in[5];
    const float* W_t1  = (const float*)d_in[6];
    const float* b_t1  = (const float*)d_in[7];
    const float* W_t2  = (const float*)d_in[8];
    const float* b_t2  = (const float*)d_in[9];
    const float* temp  = (const float*)d_in[10];

    float* out     = (float*)d_out;             // decoded [256, 29999]
    float* out_enc = (float*)d_out + DEC_ELEMS; // encoded [256, 256]

    float* He;    cudaGetSymbolAddress((void**)&He,    g_He);
    float* Ht;    cudaGetSymbolAddress((void**)&Ht,    g_Ht);
    float* trans; cudaGetSymbolAddress((void**)&trans, g_trans);
    float* encn;  cudaGetSymbolAddress((void**)&encn,  g_encn);

    const int mTiles = (NUM_CARDS + 127) / 128;   // 235

    // K1: H_e = relu(cards @ W_e1 + b_e1)
    sgemm_nn<0><<<dim3(HIDDEN / 128, mTiles), 256>>>(cards, W_e1, b_e1, He,
                                                     NUM_CARDS, HIDDEN, CARD_DIM);
    // K2: H_t = relu(cards @ W_t1 + b_t1)
    sgemm_nn<0><<<dim3(HIDDEN / 128, mTiles), 256>>>(cards, W_t1, b_t1, Ht,
                                                     NUM_CARDS, HIDDEN, CARD_DIM);
    // K3: trans = H_t[1:] @ W_t2 + b_t2   (M = 29999)
    sgemm_nn<1><<<dim3(EMBED / 128, (NM1 + 127) / 128), 256>>>(Ht + HIDDEN, W_t2, b_t2,
                                                               trans, NM1, EMBED, HIDDEN);
    // K4: l2-normalize transformed rows in place
    norm_rows<<<NM1, 256>>>(trans, NM1);
    // K5: gather-mean + encode + normalize
    pool_encode<<<BATCH, 256>>>(cube, W_e2, b_e2, out_enc);
    // K6: sims + sigmoid
    sims_kernel<<<dim3((NM1 + 127) / 128, BATCH / 128), 256>>>(encn, trans, temp, out);
}